// round 6
// baseline (speedup 1.0000x reference)
#include <cuda_runtime.h>
#include <cstdint>

// ---------------------------------------------------------------------------
// IoU loss (2D + scatter-rebuilt 3D) without materializing the 3D volume.
//   inter2 = sum over DISTINCT voxels (dedup via 2MB bitmap atomicOr) of
//            winner * m3[voxel];  union2 = sum(winner) + sum(m3) - inter2.
// Software-interleaved streams + gathers; this round: occupancy push
// (__launch_bounds__(256,8) -> 64 warps/SM) and L2-only gathers (__ldcg).
// ---------------------------------------------------------------------------

#define DMAX   256
#define BITN   ((DMAX * DMAX * DMAX) / 32)   // 512K words = 2MB

__device__ unsigned g_bitmap[BITN];
__device__ double   g_acc[5];
// [0]=S(o2*m2) [1]=S(o2+m2) [2]=S(win*m3) [3]=S(win) [4]=S(m3)
__device__ unsigned g_done;

// ---------------------------------------------------------------------------
__global__ void zero_kernel() {
    const int tid    = blockIdx.x * blockDim.x + threadIdx.x;
    const int stride = gridDim.x * blockDim.x;
    uint4* b4 = reinterpret_cast<uint4*>(g_bitmap);
    const uint4 z = make_uint4(0u, 0u, 0u, 0u);
    for (int i = tid; i < BITN / 4; i += stride) b4[i] = z;
    if (tid < 5) g_acc[tid] = 0.0;
    if (tid == 5) g_done = 0u;
}

// ---------------------------------------------------------------------------
__device__ __forceinline__ void block_reduce_pair(float a, float b,
                                                  double* accA, double* accB) {
    #pragma unroll
    for (int o = 16; o > 0; o >>= 1) {
        a += __shfl_xor_sync(0xFFFFFFFFu, a, o);
        b += __shfl_xor_sync(0xFFFFFFFFu, b, o);
    }
    __shared__ float sa[32], sb[32];
    const int lane = threadIdx.x & 31;
    const int wrp  = threadIdx.x >> 5;
    __syncthreads();
    if (lane == 0) { sa[wrp] = a; sb[wrp] = b; }
    __syncthreads();
    if (wrp == 0) {
        const int nw = (blockDim.x + 31) >> 5;
        a = (lane < nw) ? sa[lane] : 0.f;
        b = (lane < nw) ? sb[lane] : 0.f;
        #pragma unroll
        for (int o = 16; o > 0; o >>= 1) {
            a += __shfl_xor_sync(0xFFFFFFFFu, a, o);
            b += __shfl_xor_sync(0xFFFFFFFFu, b, o);
        }
        if (lane == 0) {
            atomicAdd(accA, (double)a);
            atomicAdd(accB, (double)b);
        }
    }
}

// ---------------------------------------------------------------------------
__device__ __forceinline__ void process_sample(const float* __restrict__ o2d,
                                               const float* __restrict__ m3d,
                                               int id, int x, int y, int z, int D,
                                               float& inter2, float& sumv) {
    const unsigned vox = ((unsigned)x * (unsigned)D + (unsigned)y) * (unsigned)D
                       + (unsigned)z;
    const float v = __ldcg(o2d + id);    // L2-only: no L1 pollution
    const float m = __ldcg(m3d + vox);
    const unsigned bit = 1u << (vox & 31u);
    const unsigned old = atomicOr(&g_bitmap[vox >> 5], bit);
    if (!(old & bit)) { inter2 += v * m; sumv += v; }
}

// ---------------------------------------------------------------------------
__global__ void __launch_bounds__(256, 8)
fused_kernel(const float* __restrict__ o2d,
             const float* __restrict__ m2d,
             const float* __restrict__ m3d,
             const int*   __restrict__ index,
             const int*   __restrict__ midxyz,
             int N, int M, int V, int D,
             float* __restrict__ out) {
    const int tid    = blockIdx.x * blockDim.x + threadIdx.x;
    const int stride = gridDim.x * blockDim.x;

    float inter2 = 0.f, sumv = 0.f;   // 3D scattered part
    float sm3 = 0.f;                  // sum(mask3D)
    float a2 = 0.f, b2 = 0.f;         // 2D part

    const int n_iter = N >> 2;        // 4 samples / iteration
    const int v4     = V >> 2;        // m3d float4 count
    const int m4n    = M >> 2;        // 2D float4 count

    const int4*   idx4 = reinterpret_cast<const int4*>(index);
    const int4*   mid4 = reinterpret_cast<const int4*>(midxyz);
    const float4* m34  = reinterpret_cast<const float4*>(m3d);
    const float4* o4   = reinterpret_cast<const float4*>(o2d);
    const float4* q4   = reinterpret_cast<const float4*>(m2d);

    // ======== main interleaved loop: streams + gathers together ========
    for (int i = tid; i < n_iter; i += stride) {
        // ---- stream: up to 4 coalesced m3d float4 (sub-streams k*n_iter+i) ----
        #pragma unroll
        for (int k = 0; k < 4; ++k) {
            const int j = k * n_iter + i;
            if (j < v4) {
                const float4 m = m34[j];               // stays in L2 for gathers
                sm3 += (m.x + m.y) + (m.z + m.w);
            }
        }
        // ---- stream: one 2D float4 pair ----
        if (i < m4n) {
            const float4 o = o4[i];                    // o2d reused by gathers
            const float4 m = __ldcs(q4 + i);           // one-shot: evict-first
            a2 += o.x * m.x + o.y * m.y + o.z * m.z + o.w * m.w;
            b2 += (o.x + m.x) + (o.y + m.y) + (o.z + m.z) + (o.w + m.w);
        }
        // ---- gather: 4 scattered samples ----
        const int4 id = __ldcs(idx4 + i);
        const int4 ma = __ldcs(mid4 + 3 * i + 0);
        const int4 mb = __ldcs(mid4 + 3 * i + 1);
        const int4 mc = __ldcs(mid4 + 3 * i + 2);
        process_sample(o2d, m3d, id.x, ma.x, ma.y, ma.z, D, inter2, sumv);
        process_sample(o2d, m3d, id.y, ma.w, mb.x, mb.y, D, inter2, sumv);
        process_sample(o2d, m3d, id.z, mb.z, mb.w, mc.x, D, inter2, sumv);
        process_sample(o2d, m3d, id.w, mc.y, mc.z, mc.w, D, inter2, sumv);
    }

    // ======== generic tails (no-ops for the benchmark shapes) ========
    for (int i = (n_iter << 2) + tid; i < N; i += stride) {
        process_sample(o2d, m3d, index[i],
                       midxyz[3 * i], midxyz[3 * i + 1], midxyz[3 * i + 2],
                       D, inter2, sumv);
    }
    for (int j = 4 * n_iter + tid; j < v4; j += stride) {
        const float4 m = m34[j];
        sm3 += (m.x + m.y) + (m.z + m.w);
    }
    for (int i = (v4 << 2) + tid; i < V; i += stride) sm3 += m3d[i];
    for (int i = n_iter + tid; i < m4n; i += stride) {
        const float4 o = o4[i];
        const float4 m = q4[i];
        a2 += o.x * m.x + o.y * m.y + o.z * m.z + o.w * m.w;
        b2 += (o.x + m.x) + (o.y + m.y) + (o.z + m.z) + (o.w + m.w);
    }
    for (int i = (m4n << 2) + tid; i < M; i += stride) {
        const float o = o2d[i], m = m2d[i];
        a2 += o * m;
        b2 += o + m;
    }

    block_reduce_pair(a2, b2, &g_acc[0], &g_acc[1]);
    block_reduce_pair(inter2, sumv, &g_acc[2], &g_acc[3]);
    block_reduce_pair(sm3, 0.f, &g_acc[4], &g_acc[4]);

    // ======== fused finalize: last block computes the loss ========
    __syncthreads();
    if (threadIdx.x == 0) {
        __threadfence();
        const unsigned t = atomicAdd(&g_done, 1u);
        if (t == gridDim.x - 1u) {
            const double eps = 1e-8;
            const double A1 = g_acc[0], B1 = g_acc[1];
            const double I2 = g_acc[2], SV = g_acc[3], SM = g_acc[4];
            const double l1 = 1.0 - (A1 + eps) / ((B1 - A1) + eps);
            const double l2 = 1.0 - (I2 + eps) / ((SV + SM - I2) + eps);
            out[0] = (float)l1;
            out[1] = (float)l2;
            out[2] = (float)(l1 + l2);
        }
    }
}

// ---------------------------------------------------------------------------
extern "C" void kernel_launch(void* const* d_in, const int* in_sizes, int n_in,
                              void* d_out, int out_size) {
    const float* o2d    = (const float*)d_in[0];
    const float* m2d    = (const float*)d_in[1];
    const float* m3d    = (const float*)d_in[2];
    const int*   index  = (const int*)  d_in[3];
    const int*   midxyz = (const int*)  d_in[4];

    const int M = in_sizes[0];        // H2*W2
    const int V = in_sizes[2];        // D^3
    const int N = in_sizes[3];        // samples

    int D = 1;
    while ((long long)(D + 1) * (D + 1) * (D + 1) <= (long long)V) ++D;
    if (D > DMAX) D = DMAX;

    float* out = (float*)d_out;

    const int TPB  = 256;
    const int GRID = 148 * 16;        // 2368 blocks = 2 full waves at occ 8

    zero_kernel<<<148 * 8, TPB>>>();
    fused_kernel<<<GRID, TPB>>>(o2d, m2d, m3d, index, midxyz, N, M, V, D, out);
}